// round 3
// baseline (speedup 1.0000x reference)
#include <cuda_runtime.h>
#include <cstddef>

#define NCOL 2048
#define NROW 16384
#define THREADS 128
#define RPB 128                 // rows per block (1 thread per row)
#define W 64                    // tile width (columns)
#define NT (NCOL / W)           // 32 tiles
#define LDW 68                  // padded smem row stride in floats (272B = 17*16B)
#define TILE_F (RPB * LDW)      // floats per tile buffer
// smem: cs table (2048 float2 = 4096 floats) + 3 input tiles + 2 output tiles
#define SMEM_FLOATS (2 * NCOL + 3 * TILE_F + 2 * TILE_F)
#define SMEM_BYTES (SMEM_FLOATS * 4)

__device__ __forceinline__ void cp_async16(float* smem_dst, const float* gsrc) {
    unsigned s = (unsigned)__cvta_generic_to_shared(smem_dst);
    asm volatile("cp.async.cg.shared.global [%0], [%1], 16;" :: "r"(s), "l"(gsrc));
}
__device__ __forceinline__ void cp_commit() { asm volatile("cp.async.commit_group;"); }

__global__ void __launch_bounds__(THREADS, 1)
ring_givens_kernel(const float* __restrict__ x,
                   const float* __restrict__ angles,
                   float* __restrict__ out) {
    extern __shared__ float smem[];
    float2* cs = (float2*)smem;                 // [2048] (cos, sin)
    float*  sin_tiles = smem + 2 * NCOL;        // 3 input tiles
    float*  sot       = sin_tiles + 3 * TILE_F; // 2 output staging tiles

    const int tid  = threadIdx.x;
    const int row0 = blockIdx.x * RPB;
    const int row  = row0 + tid;

    // --- prefetch first 3 tiles (highest column tiles first) ---
    #pragma unroll
    for (int p = 0; p < 3; ++p) {
        int it = NT - 1 - p;
        float* buf = sin_tiles + (it % 3) * TILE_F;
        #pragma unroll
        for (int j = 0; j < 16; ++j) {
            int q  = tid + j * THREADS;
            int r  = q >> 4;            // 16 float4-chunks per 64-wide row
            int c4 = (q & 15) << 2;
            cp_async16(buf + r * LDW + c4,
                       x + (size_t)(row0 + r) * NCOL + it * W + c4);
        }
        cp_commit();
    }

    // --- cos/sin table (overlaps with prefetch) ---
    for (int k = tid; k < NCOL; k += THREADS) {
        float sv, cv;
        sincosf(angles[k], &sv, &cv);
        cs[k] = make_float2(cv, sv);
    }

    // x[row][0] needed by the wrap rotation (k = 2047 pairs indices 2047 and 0)
    float x0 = x[(size_t)row * NCOL];

    const float4* csf4 = (const float4*)cs;  // csf4[m] = {c(2m), s(2m), c(2m+1), s(2m+1)}

    float t = 0.f, v0run = 0.f;
    float c0r = 0.f, c1r = 0.f, c2r = 0.f;   // carried outputs (slots +1,+2,+3)

    for (int i = NT - 1; i >= 0; --i) {
        asm volatile("cp.async.wait_group 2;");
        __syncthreads();   // tile i visible to all; prev output buffer fully stored

        const float* bin = sin_tiles + (i % 3) * TILE_F + tid * LDW;
        float* otc = sot + (i & 1) * TILE_F + tid * LDW;        // range [k0, k0+W)
        float* otn = sot + ((i + 1) & 1) * TILE_F + tid * LDW;  // range [k0+W, k0+2W)
        const int k0 = i * W;

        #pragma unroll
        for (int q = 15; q >= 0; --q) {
            float4 u4 = *(const float4*)(bin + 4 * q);
            float4 cB = csf4[(k0 >> 1) + 2 * q];      // k0+4q, k0+4q+1
            float4 cA = csf4[(k0 >> 1) + 2 * q + 1];  // k0+4q+2, k0+4q+3

            if (i == NT - 1 && q == 15) {
                // wrap rotation k = 2047: plane (2047, 0). No output yet.
                t     = cA.z * u4.w - cA.w * x0;
                v0run = cA.w * u4.w + cA.z * x0;
            } else {
                // step k = k0+4q+3 -> out[k0+4q+4]
                float O3 = cA.w * u4.w + cA.z * t;
                t        = cA.z * u4.w - cA.w * t;
                float4 st4 = make_float4(O3, c0r, c1r, c2r);
                if (q == 15) *(float4*)otn = st4;               // slots 0..3 of next range
                else         *(float4*)(otc + 4 * q + 4) = st4; // slots 4q+4..4q+7
            }
            // step k = k0+4q+2 -> out slot 4q+3
            float O2 = cA.y * u4.z + cA.x * t;
            t        = cA.x * u4.z - cA.y * t;
            // step k = k0+4q+1 -> out slot 4q+2
            float O1 = cB.w * u4.y + cB.z * t;
            t        = cB.z * u4.y - cB.w * t;
            // step k = k0+4q -> out slot 4q+1 ; at the very end use wrapped v0
            float u0 = (i == 0 && q == 0) ? v0run : u4.x;
            float O0 = cB.y * u0 + cB.x * t;
            t        = cB.x * u0 - cB.y * t;
            c0r = O0; c1r = O1; c2r = O2;
        }

        __syncthreads();   // all output-staging writes visible; input buffer free

        // prefetch tile i-3 into the just-freed buffer (always commit one group
        // so wait_group 2 accounting stays uniform through the tail)
        if (i >= 3) {
            int ip = i - 3;
            float* buf = sin_tiles + (ip % 3) * TILE_F;
            #pragma unroll
            for (int j = 0; j < 16; ++j) {
                int q  = tid + j * THREADS;
                int r  = q >> 4;
                int c4 = (q & 15) << 2;
                cp_async16(buf + r * LDW + c4,
                           x + (size_t)(row0 + r) * NCOL + ip * W + c4);
            }
        }
        cp_commit();

        // store the now-complete buffer for out columns [(i+1)*W, (i+2)*W)
        if (i < NT - 1) {
            const float* sb = sot + ((i + 1) & 1) * TILE_F;
            float* ob = out + (size_t)row0 * NCOL + (i + 1) * W;
            #pragma unroll
            for (int j = 0; j < 16; ++j) {
                int q  = tid + j * THREADS;
                int r  = q >> 4;
                int c4 = (q & 15) << 2;
                *(float4*)(ob + (size_t)r * NCOL + c4) =
                    *(const float4*)(sb + r * LDW + c4);
            }
        }
    }

    // finalize buffer 0 (out columns [0, W)): slot0 = out[0] = t, slots 1..3 = carries
    *(float4*)(sot + tid * LDW) = make_float4(t, c0r, c1r, c2r);
    __syncthreads();
    {
        const float* sb = sot;
        float* ob = out + (size_t)row0 * NCOL;
        #pragma unroll
        for (int j = 0; j < 16; ++j) {
            int q  = tid + j * THREADS;
            int r  = q >> 4;
            int c4 = (q & 15) << 2;
            *(float4*)(ob + (size_t)r * NCOL + c4) =
                *(const float4*)(sb + r * LDW + c4);
        }
    }
}

extern "C" void kernel_launch(void* const* d_in, const int* in_sizes, int n_in,
                              void* d_out, int out_size) {
    const float* x      = (const float*)d_in[0];
    const float* angles = (const float*)d_in[1];
    // defensive: x is the big tensor (B*N), angles is length N
    if (n_in >= 2 && in_sizes[0] < in_sizes[1]) {
        x      = (const float*)d_in[1];
        angles = (const float*)d_in[0];
    }
    float* out = (float*)d_out;

    cudaFuncSetAttribute(ring_givens_kernel,
                         cudaFuncAttributeMaxDynamicSharedMemorySize, SMEM_BYTES);
    ring_givens_kernel<<<NROW / RPB, THREADS, SMEM_BYTES>>>(x, angles, out);
}

// round 5
// speedup vs baseline: 1.0539x; 1.0539x over previous
#include <cuda_runtime.h>
#include <cstddef>

#define NCOL 2048
#define NROW 16384
#define THREADS 128
#define WPB 4                    // warps per block
#define RPW 28                   // rows per warp (lanes 28..31 are pad)
#define RPB (WPB * RPW)          // 112 rows per block
#define W 64                     // tile width (columns)
#define NT (NCOL / W)            // 32 tiles
#define LDW 68                   // padded smem row stride in floats (272B)
#define TILE_F (RPW * LDW)       // 1904 floats per tile buffer
#define NIN 4                    // input ring depth (per warp)
#define WBUF_F ((NIN + 2) * TILE_F)   // per-warp buffer floats
#define SMEM_FLOATS (2 * NCOL + WPB * WBUF_F)
#define SMEM_BYTES (SMEM_FLOATS * 4)  // 16KB cs + 4*44.6KB = ~199KB
#define CHUNKS_PER_LANE ((RPW * (W / 4)) / 32)   // 448/32 = 14

__device__ __forceinline__ void cp_async16(float* smem_dst, const float* gsrc) {
    unsigned s = (unsigned)__cvta_generic_to_shared(smem_dst);
    asm volatile("cp.async.cg.shared.global [%0], [%1], 16;" :: "r"(s), "l"(gsrc));
}
__device__ __forceinline__ void cp_commit() { asm volatile("cp.async.commit_group;"); }

__global__ void __launch_bounds__(THREADS, 1)
ring_givens_kernel(const float* __restrict__ x,
                   const float* __restrict__ angles,
                   float* __restrict__ out) {
    extern __shared__ float smem[];
    float2* cs = (float2*)smem;                       // [2048] (cos, sin)
    const int tid  = threadIdx.x;
    const int wid  = tid >> 5;
    const int lane = tid & 31;

    float* inb = smem + 2 * NCOL + wid * WBUF_F;      // NIN input tiles
    float* otb = inb + NIN * TILE_F;                  // 2 output staging tiles

    const long long wgid = (long long)blockIdx.x * WPB + wid;
    const long long base = wgid * RPW;                // first row of this warp
    const bool active = (base < NROW);

    // --- prefetch first NIN tiles (highest column tiles first), warp-private ---
    if (active) {
        #pragma unroll
        for (int p = 0; p < NIN; ++p) {
            int it = NT - 1 - p;
            float* buf = inb + (it & (NIN - 1)) * TILE_F;
            #pragma unroll
            for (int j = 0; j < CHUNKS_PER_LANE; ++j) {
                int q  = lane + j * 32;
                int r  = q >> 4;                       // local row 0..27
                int c4 = (q & 15) << 2;
                long long grow = base + r;
                if (grow >= NROW) grow = NROW - 1;     // clamp (tail warps)
                cp_async16(buf + r * LDW + c4,
                           x + grow * NCOL + it * W + c4);
            }
            cp_commit();
        }
    }

    // --- cos/sin table (block-cooperative, overlaps the prefetches) ---
    for (int k = tid; k < NCOL; k += THREADS) {
        float sv, cv;
        sincosf(angles[k], &sv, &cv);
        cs[k] = make_float2(cv, sv);
    }
    __syncthreads();          // only block barrier in the kernel
    if (!active) return;

    const int cl = (lane < RPW) ? lane : (RPW - 1);   // clamped compute lane
    const bool wr = (lane < RPW);
    long long rowc = base + cl;
    if (rowc >= NROW) rowc = NROW - 1;
    const float x0 = x[rowc * NCOL];                  // wrap partner of col 2047

    const float4* csf4 = (const float4*)cs;  // {c(2m), s(2m), c(2m+1), s(2m+1)}

    float t = 0.f, v0run = 0.f;
    float c0r = 0.f, c1r = 0.f, c2r = 0.f;            // carried outputs

    for (int i = NT - 1; i >= 0; --i) {
        asm volatile("cp.async.wait_group %0;" :: "n"(NIN - 1));
        __syncwarp();      // tile i visible warp-wide; prev store loop drained

        const float* bin = inb + (i & (NIN - 1)) * TILE_F + cl * LDW;
        float* otc = otb + (i & 1) * TILE_F + cl * LDW;        // cols [k0, k0+W)
        float* otn = otb + ((i + 1) & 1) * TILE_F + cl * LDW;  // cols [k0+W, ..)
        const int k0 = i * W;

        #pragma unroll
        for (int q = 15; q >= 0; --q) {
            float4 u4 = *(const float4*)(bin + 4 * q);
            float4 cB = csf4[(k0 >> 1) + 2 * q];      // k0+4q, k0+4q+1
            float4 cA = csf4[(k0 >> 1) + 2 * q + 1];  // k0+4q+2, k0+4q+3

            if (i == NT - 1 && q == 15) {
                // wrap rotation k = 2047: plane (2047, 0). No output yet.
                t     = cA.z * u4.w - cA.w * x0;
                v0run = cA.w * u4.w + cA.z * x0;
            } else {
                // step k = k0+4q+3 -> out[k0+4q+4]
                float O3 = cA.w * u4.w + cA.z * t;
                t        = cA.z * u4.w - cA.w * t;
                float4 st4 = make_float4(O3, c0r, c1r, c2r);
                if (wr) {
                    if (q == 15) *(float4*)otn = st4;                // slots 0..3
                    else         *(float4*)(otc + 4 * q + 4) = st4;  // 4q+4..4q+7
                }
            }
            float O2 = cA.y * u4.z + cA.x * t;   // k0+4q+2 -> slot 4q+3
            t        = cA.x * u4.z - cA.y * t;
            float O1 = cB.w * u4.y + cB.z * t;   // k0+4q+1 -> slot 4q+2
            t        = cB.z * u4.y - cB.w * t;
            float u0 = (i == 0 && q == 0) ? v0run : u4.x;
            float O0 = cB.y * u0 + cB.x * t;     // k0+4q   -> slot 4q+1
            t        = cB.x * u0 - cB.y * t;
            c0r = O0; c1r = O1; c2r = O2;
        }

        __syncwarp();      // all lanes done reading inbuf slot + staging writes

        // prefetch tile i-NIN into the just-freed slot (slot (i-NIN)&3 == i&3);
        // always commit so wait_group accounting stays uniform in the tail
        if (i >= NIN) {
            int ip = i - NIN;
            float* buf = inb + (i & (NIN - 1)) * TILE_F;
            #pragma unroll
            for (int j = 0; j < CHUNKS_PER_LANE; ++j) {
                int q  = lane + j * 32;
                int r  = q >> 4;
                int c4 = (q & 15) << 2;
                long long grow = base + r;
                if (grow >= NROW) grow = NROW - 1;
                cp_async16(buf + r * LDW + c4,
                           x + grow * NCOL + ip * W + c4);
            }
        }
        cp_commit();

        // store the now-complete buffer: out columns [(i+1)*W, (i+2)*W)
        if (i < NT - 1) {
            const float* sb = otb + ((i + 1) & 1) * TILE_F;
            const int col0 = (i + 1) * W;
            #pragma unroll
            for (int j = 0; j < CHUNKS_PER_LANE; ++j) {
                int q  = lane + j * 32;
                int r  = q >> 4;
                int c4 = (q & 15) << 2;
                long long grow = base + r;
                if (grow < NROW)
                    *(float4*)(out + grow * NCOL + col0 + c4) =
                        *(const float4*)(sb + r * LDW + c4);
            }
        }
    }

    // finalize buffer parity 0 (out columns [0, W)): slot0 = {out[0]=t, carries}
    if (wr) *(float4*)(otb + cl * LDW) = make_float4(t, c0r, c1r, c2r);
    __syncwarp();
    {
        const float* sb = otb;
        #pragma unroll
        for (int j = 0; j < CHUNKS_PER_LANE; ++j) {
            int q  = lane + j * 32;
            int r  = q >> 4;
            int c4 = (q & 15) << 2;
            long long grow = base + r;
            if (grow < NROW)
                *(float4*)(out + grow * NCOL + c4) =
                    *(const float4*)(sb + r * LDW + c4);
        }
    }
}

extern "C" void kernel_launch(void* const* d_in, const int* in_sizes, int n_in,
                              void* d_out, int out_size) {
    const float* x      = (const float*)d_in[0];
    const float* angles = (const float*)d_in[1];
    if (n_in >= 2 && in_sizes[0] < in_sizes[1]) {   // defensive ordering
        x      = (const float*)d_in[1];
        angles = (const float*)d_in[0];
    }
    float* out = (float*)d_out;

    cudaFuncSetAttribute(ring_givens_kernel,
                         cudaFuncAttributeMaxDynamicSharedMemorySize, SMEM_BYTES);
    int grid = (NROW + RPB - 1) / RPB;   // 147
    ring_givens_kernel<<<grid, THREADS, SMEM_BYTES>>>(x, angles, out);
}